// round 2
// baseline (speedup 1.0000x reference)
#include <cuda_runtime.h>
#include <math.h>

#define D_MODEL 1024
#define N_HEADS 16
#define D_HEAD  64
#define B_SZ    4
#define T_LEN   2048
#define M_ROWS  (B_SZ * T_LEN)   // 8192

// ---------------- scratch (static device globals; no allocs) ----------------
__device__ float g_q [(size_t)M_ROWS * D_MODEL];   // [B,H,T,Dh]
__device__ float g_k [(size_t)M_ROWS * D_MODEL];
__device__ float g_v [(size_t)M_ROWS * D_MODEL];
__device__ float g_ao[(size_t)M_ROWS * D_MODEL];   // [B,T,D] pre-Wo
__device__ float g_tab[N_HEADS * 4096];            // bias per head per (k-q+2047)

// ---------------- bias bucket table ----------------
__global__ void bias_tab_kernel(const float* __restrict__ rel_emb)
{
    int idx = blockIdx.x * blockDim.x + threadIdx.x;
    if (idx >= N_HEADS * 4095) return;
    int h  = idx / 4095;
    int dp = idx % 4095;        // 0..4094
    int r  = dp - 2047;         // k - q
    int bucket = (r > 0) ? 16 : 0;
    int rp = (r < 0) ? -r : r;
    int rel;
    if (rp < 8) {
        rel = rp;
    } else {
        // matches jax: log(rp/8)/log(16) * 8, truncated, clamped to 15
        float v = (logf((float)rp * 0.125f) / 2.772588722239781f) * 8.0f;
        rel = 8 + (int)v;
        if (rel > 15) rel = 15;
    }
    bucket += rel;
    g_tab[h * 4096 + dp] = rel_emb[bucket * N_HEADS + h];
}

// ---------------- position_bias tensor writer ----------------
__global__ void bias_out_kernel(float* __restrict__ out)
{
    const size_t n4 = (size_t)N_HEADS * T_LEN * T_LEN / 4;
    for (size_t i = (size_t)blockIdx.x * blockDim.x + threadIdx.x; i < n4;
         i += (size_t)gridDim.x * blockDim.x) {
        size_t e = i * 4;
        int k = (int)(e & 2047);
        size_t qh = e >> 11;
        int q = (int)(qh & 2047);
        int h = (int)(qh >> 11);
        const float* t = &g_tab[h * 4096 + (k - q) + 2047];
        float4 v = make_float4(t[0], t[1], t[2], t[3]);
        *(float4*)&out[e] = v;
    }
}

// ---------------- fp32 GEMM: Y = X @ W^T ----------------
// X [M,1024] row-major, W [1024,1024] row-major (dot rows of X with rows of W).
// permute=1: write Y as [B,H,T,Dh]; permute=0: plain [M,1024].
__global__ __launch_bounds__(256, 2) void gemm128(
    const float* __restrict__ X, const float* __restrict__ W,
    float* __restrict__ Y, int permute)
{
    __shared__ float As[16][132];
    __shared__ float Bs[16][132];
    const int tid = threadIdx.x;
    const int bm = blockIdx.y * 128;
    const int bn = blockIdx.x * 128;
    const int tx = tid & 15, ty = tid >> 4;
    const int row0 = ty * 8, col0 = tx * 8;
    const int lr = tid >> 2;          // 0..63
    const int lk = (tid & 3) << 2;    // 0,4,8,12

    float acc[8][8];
#pragma unroll
    for (int i = 0; i < 8; i++)
#pragma unroll
        for (int j = 0; j < 8; j++) acc[i][j] = 0.f;

    const float* xa = X + (size_t)(bm + lr) * 1024 + lk;
    const float* xb = X + (size_t)(bm + lr + 64) * 1024 + lk;
    const float* wa = W + (size_t)(bn + lr) * 1024 + lk;
    const float* wb = W + (size_t)(bn + lr + 64) * 1024 + lk;

    float4 a0 = *(const float4*)xa;
    float4 a1 = *(const float4*)xb;
    float4 b0 = *(const float4*)wa;
    float4 b1 = *(const float4*)wb;

    for (int k0 = 0; k0 < 1024; k0 += 16) {
        __syncthreads();
        As[lk + 0][lr] = a0.x; As[lk + 1][lr] = a0.y; As[lk + 2][lr] = a0.z; As[lk + 3][lr] = a0.w;
        As[lk + 0][lr + 64] = a1.x; As[lk + 1][lr + 64] = a1.y; As[lk + 2][lr + 64] = a1.z; As[lk + 3][lr + 64] = a1.w;
        Bs[lk + 0][lr] = b0.x; Bs[lk + 1][lr] = b0.y; Bs[lk + 2][lr] = b0.z; Bs[lk + 3][lr] = b0.w;
        Bs[lk + 0][lr + 64] = b1.x; Bs[lk + 1][lr + 64] = b1.y; Bs[lk + 2][lr + 64] = b1.z; Bs[lk + 3][lr + 64] = b1.w;
        __syncthreads();
        if (k0 + 16 < 1024) {   // prefetch next slab (hides LDG under compute)
            a0 = *(const float4*)(xa + k0 + 16);
            a1 = *(const float4*)(xb + k0 + 16);
            b0 = *(const float4*)(wa + k0 + 16);
            b1 = *(const float4*)(wb + k0 + 16);
        }
#pragma unroll
        for (int kk = 0; kk < 16; kk++) {
            float a[8], b[8];
            *(float4*)&a[0] = *(const float4*)&As[kk][row0];
            *(float4*)&a[4] = *(const float4*)&As[kk][row0 + 4];
            *(float4*)&b[0] = *(const float4*)&Bs[kk][col0];
            *(float4*)&b[4] = *(const float4*)&Bs[kk][col0 + 4];
#pragma unroll
            for (int i = 0; i < 8; i++)
#pragma unroll
                for (int j = 0; j < 8; j++)
                    acc[i][j] = fmaf(a[i], b[j], acc[i][j]);
        }
    }

#pragma unroll
    for (int i = 0; i < 8; i++) {
        int mrow = bm + row0 + i;
        if (!permute) {
            *(float4*)&Y[(size_t)mrow * 1024 + bn + col0] =
                make_float4(acc[i][0], acc[i][1], acc[i][2], acc[i][3]);
            *(float4*)&Y[(size_t)mrow * 1024 + bn + col0 + 4] =
                make_float4(acc[i][4], acc[i][5], acc[i][6], acc[i][7]);
        } else {
            int b = mrow >> 11, t = mrow & 2047;
#pragma unroll
            for (int half = 0; half < 2; half++) {
                int n = bn + col0 + half * 4;
                int hh = n >> 6, d = n & 63;
                *(float4*)&Y[(((size_t)(b * 16 + hh) * 2048 + t) << 6) + d] =
                    make_float4(acc[i][half * 4 + 0], acc[i][half * 4 + 1],
                                acc[i][half * 4 + 2], acc[i][half * 4 + 3]);
            }
        }
    }
}

// ---------------- flash attention (fp32) ----------------
// One block per (b*H+h, q-tile of 128). KTILE = 64. 256 threads (16x16),
// thread tile: 8 q-rows x 4 k-cols (S) / 8 q-rows x 4 dv-cols (O).
#define QT 128
#define KT 64
#define QS_STRIDE 132
#define KS_STRIDE 68
#define SM_QS 0
#define SM_KS (64 * QS_STRIDE)            // 8448
#define SM_VS (SM_KS + 64 * KS_STRIDE)    // 12800
#define SM_PS (SM_VS + 64 * 64)           // 16896
#define SM_BS (SM_PS + 128 * 64)          // 25088
#define SM_FLOATS (SM_BS + 256)           // 25344 floats = 101376 B

__global__ __launch_bounds__(256, 2) void attn_kernel()
{
    extern __shared__ float smf[];
    float* Qs = smf + SM_QS;   // [d][r] transposed
    float* Ks = smf + SM_KS;   // [d][c] transposed
    float* Vs = smf + SM_VS;   // [c][dv]
    float* Ps = smf + SM_PS;   // [r][c]
    float* bs = smf + SM_BS;   // bias window, 192 entries

    const int tid = threadIdx.x;
    const int bh  = blockIdx.y;           // b*16 + h
    const int h   = bh & 15;
    const int q0  = blockIdx.x * QT;
    const float* qb = g_q + (size_t)bh * T_LEN * 64;
    const float* kb = g_k + (size_t)bh * T_LEN * 64;
    const float* vb = g_v + (size_t)bh * T_LEN * 64;

    // load Q tile transposed
#pragma unroll
    for (int i = 0; i < 8; i++) {
        int f = tid + i * 256;
        int r = f >> 4;
        int d4 = (f & 15) << 2;
        float4 v = *(const float4*)&qb[(size_t)(q0 + r) * 64 + d4];
        Qs[(d4 + 0) * QS_STRIDE + r] = v.x;
        Qs[(d4 + 1) * QS_STRIDE + r] = v.y;
        Qs[(d4 + 2) * QS_STRIDE + r] = v.z;
        Qs[(d4 + 3) * QS_STRIDE + r] = v.w;
    }

    const int tx = tid & 15, ty = tid >> 4;
    const int row0 = ty * 8, col0 = tx * 4;

    float m[8], l[8], o[8][4];
#pragma unroll
    for (int i = 0; i < 8; i++) {
        m[i] = -1e30f; l[i] = 0.f;
#pragma unroll
        for (int j = 0; j < 4; j++) o[i][j] = 0.f;
    }

    for (int kt = 0; kt < T_LEN; kt += KT) {
        __syncthreads();
#pragma unroll
        for (int i = 0; i < 4; i++) {
            int f = tid + i * 256;
            int c = f >> 4;
            int d4 = (f & 15) << 2;
            float4 v = *(const float4*)&kb[(size_t)(kt + c) * 64 + d4];
            Ks[(d4 + 0) * KS_STRIDE + c] = v.x;
            Ks[(d4 + 1) * KS_STRIDE + c] = v.y;
            Ks[(d4 + 2) * KS_STRIDE + c] = v.z;
            Ks[(d4 + 3) * KS_STRIDE + c] = v.w;
        }
#pragma unroll
        for (int i = 0; i < 4; i++) {
            int f = tid + i * 256;
            *(float4*)&Vs[f * 4] = *(const float4*)&vb[(size_t)kt * 64 + f * 4];
        }
        // bias window: (k-q) = (kt-q0) + ((col)-(row)); local range [-127, 63]
        if (tid < 192) bs[tid] = g_tab[h * 4096 + (kt - q0) + tid + 1920];
        __syncthreads();

        // S = Q K^T
        float s[8][4];
#pragma unroll
        for (int i = 0; i < 8; i++)
#pragma unroll
            for (int j = 0; j < 4; j++) s[i][j] = 0.f;

#pragma unroll 8
        for (int d = 0; d < 64; d++) {
            float4 qa = *(const float4*)&Qs[d * QS_STRIDE + row0];
            float4 qc = *(const float4*)&Qs[d * QS_STRIDE + row0 + 4];
            float4 kv = *(const float4*)&Ks[d * KS_STRIDE + col0];
            float qv[8] = {qa.x, qa.y, qa.z, qa.w, qc.x, qc.y, qc.z, qc.w};
            float kk4[4] = {kv.x, kv.y, kv.z, kv.w};
#pragma unroll
            for (int i = 0; i < 8; i++)
#pragma unroll
                for (int j = 0; j < 4; j++)
                    s[i][j] = fmaf(qv[i], kk4[j], s[i][j]);
        }

        // scale + bias + online softmax (row reduce over 16 lanes)
#pragma unroll
        for (int i = 0; i < 8; i++) {
            int base = col0 - (row0 + i) + 127;
#pragma unroll
            for (int j = 0; j < 4; j++)
                s[i][j] = fmaf(s[i][j], 0.125f, bs[base + j]);
            float mt = fmaxf(fmaxf(s[i][0], s[i][1]), fmaxf(s[i][2], s[i][3]));
#pragma unroll
            for (int off = 1; off < 16; off <<= 1)
                mt = fmaxf(mt, __shfl_xor_sync(0xffffffffu, mt, off, 16));
            float mn = fmaxf(m[i], mt);
            float corr = expf(m[i] - mn);
            float sum = 0.f;
#pragma unroll
            for (int j = 0; j < 4; j++) {
                float p = expf(s[i][j] - mn);
                s[i][j] = p;
                sum += p;
            }
#pragma unroll
            for (int off = 1; off < 16; off <<= 1)
                sum += __shfl_xor_sync(0xffffffffu, sum, off, 16);
            l[i] = l[i] * corr + sum;
            m[i] = mn;
#pragma unroll
            for (int j = 0; j < 4; j++) o[i][j] *= corr;
            *(float4*)&Ps[(row0 + i) * 64 + col0] =
                make_float4(s[i][0], s[i][1], s[i][2], s[i][3]);
        }
        __syncthreads();

        // O += P V
#pragma unroll 4
        for (int c = 0; c < 64; c++) {
            float4 vv = *(const float4*)&Vs[c * 64 + col0];
#pragma unroll
            for (int i = 0; i < 8; i++) {
                float p = Ps[(row0 + i) * 64 + c];
                o[i][0] = fmaf(p, vv.x, o[i][0]);
                o[i][1] = fmaf(p, vv.y, o[i][1]);
                o[i][2] = fmaf(p, vv.z, o[i][2]);
                o[i][3] = fmaf(p, vv.w, o[i][3]);
            }
        }
    }

    const int b = bh >> 4;
#pragma unroll
    for (int i = 0; i < 8; i++) {
        float inv = 1.f / l[i];
        *(float4*)&g_ao[(size_t)(b * T_LEN + q0 + row0 + i) * 1024 + h * 64 + col0] =
            make_float4(o[i][0] * inv, o[i][1] * inv, o[i][2] * inv, o[i][3] * inv);
    }
}

// ---------------- launch ----------------
extern "C" void kernel_launch(void* const* d_in, const int* in_sizes, int n_in,
                              void* d_out, int out_size)
{
    const float* query = (const float*)d_in[0];
    const float* key_  = (const float*)d_in[1];
    const float* value = (const float*)d_in[2];
    const float* Wq  = (const float*)d_in[3];
    const float* Wk  = (const float*)d_in[4];
    const float* Wv  = (const float*)d_in[5];
    const float* Wo  = (const float*)d_in[6];
    const float* rel = (const float*)d_in[7];
    float* out = (float*)d_out;

    float *gq, *gk, *gv, *gao;
    cudaGetSymbolAddress((void**)&gq,  g_q);
    cudaGetSymbolAddress((void**)&gk,  g_k);
    cudaGetSymbolAddress((void**)&gv,  g_v);
    cudaGetSymbolAddress((void**)&gao, g_ao);

    cudaFuncSetAttribute(attn_kernel, cudaFuncAttributeMaxDynamicSharedMemorySize,
                         SM_FLOATS * 4);

    bias_tab_kernel<<<256, 256>>>(rel);

    dim3 gg(8, 64);   // N/128 x M/128
    gemm128<<<gg, 256>>>(query, Wq, gq, 1);
    gemm128<<<gg, 256>>>(key_,  Wk, gk, 1);
    gemm128<<<gg, 256>>>(value, Wv, gv, 1);

    attn_kernel<<<dim3(16, 64), 256, SM_FLOATS * 4>>>();

    gemm128<<<gg, 256>>>(gao, Wo, out, 0);

    // second tuple element: position_bias [1,16,2048,2048]
    if ((long long)out_size >= 8388608LL + 67108864LL)
        bias_out_kernel<<<2048, 256>>>(out + 8388608);
}

// round 4
// speedup vs baseline: 1.3541x; 1.3541x over previous
#include <cuda_runtime.h>
#include <cuda_bf16.h>
#include <math.h>
#include <stdint.h>

#define D_MODEL 1024
#define N_HEADS 16
#define D_HEAD  64
#define B_SZ    4
#define T_LEN   2048
#define M_ROWS  (B_SZ * T_LEN)   // 8192

// ---------------- scratch (static device globals; no allocs) ----------------
__device__ float g_q [(size_t)M_ROWS * D_MODEL];   // [B,H,T,Dh]
__device__ float g_k [(size_t)M_ROWS * D_MODEL];
__device__ float g_v [(size_t)M_ROWS * D_MODEL];
__device__ float g_ao[(size_t)M_ROWS * D_MODEL];   // [B,T,D] pre-Wo
__device__ float g_tab[N_HEADS * 4096];            // bias per head per (k-q+2047)
__device__ __nv_bfloat16 g_ah[(size_t)M_ROWS * D_MODEL];  // activation hi
__device__ __nv_bfloat16 g_al[(size_t)M_ROWS * D_MODEL];  // activation lo
__device__ __nv_bfloat16 g_wh[(size_t)D_MODEL * D_MODEL]; // weight hi
__device__ __nv_bfloat16 g_wl[(size_t)D_MODEL * D_MODEL]; // weight lo

// ---------------- PTX helpers (baseline sm_103, no 'a' features) ----------------
__device__ __forceinline__ uint32_t smem_u32(const void* p) {
    uint32_t a;
    asm("{ .reg .u64 t; cvta.to.shared.u64 t, %1; cvt.u32.u64 %0, t; }" : "=r"(a) : "l"(p));
    return a;
}
__device__ __forceinline__ void cp16(uint32_t dst, const void* src) {
    asm volatile("cp.async.cg.shared.global [%0], [%1], 16;" :: "r"(dst), "l"(src));
}
#define CP_COMMIT() asm volatile("cp.async.commit_group;" ::: "memory")
#define CP_WAIT0()  asm volatile("cp.async.wait_group 0;" ::: "memory")

__device__ __forceinline__ void ldsm4(uint32_t* r, uint32_t addr) {
    asm volatile("ldmatrix.sync.aligned.m8n8.x4.shared.b16 {%0,%1,%2,%3}, [%4];"
                 : "=r"(r[0]), "=r"(r[1]), "=r"(r[2]), "=r"(r[3]) : "r"(addr));
}
__device__ __forceinline__ void mma16816(float* c, const uint32_t* a, const uint32_t* b) {
    asm volatile(
        "mma.sync.aligned.m16n8k16.row.col.f32.bf16.bf16.f32 "
        "{%0,%1,%2,%3}, {%4,%5,%6,%7}, {%8,%9}, {%0,%1,%2,%3};"
        : "+f"(c[0]), "+f"(c[1]), "+f"(c[2]), "+f"(c[3])
        : "r"(a[0]), "r"(a[1]), "r"(a[2]), "r"(a[3]), "r"(b[0]), "r"(b[1]));
}

// ---------------- bias bucket table ----------------
__global__ void bias_tab_kernel(const float* __restrict__ rel_emb)
{
    int idx = blockIdx.x * blockDim.x + threadIdx.x;
    if (idx >= N_HEADS * 4095) return;
    int h  = idx / 4095;
    int dp = idx % 4095;
    int r  = dp - 2047;
    int bucket = (r > 0) ? 16 : 0;
    int rp = (r < 0) ? -r : r;
    int rel;
    if (rp < 8) {
        rel = rp;
    } else {
        float v = (logf((float)rp * 0.125f) / 2.772588722239781f) * 8.0f;
        rel = 8 + (int)v;
        if (rel > 15) rel = 15;
    }
    bucket += rel;
    g_tab[h * 4096 + dp] = rel_emb[bucket * N_HEADS + h];
}

// ---------------- position_bias tensor writer ----------------
__global__ void bias_out_kernel(float* __restrict__ out)
{
    const size_t n4 = (size_t)N_HEADS * T_LEN * T_LEN / 4;
    for (size_t i = (size_t)blockIdx.x * blockDim.x + threadIdx.x; i < n4;
         i += (size_t)gridDim.x * blockDim.x) {
        size_t e = i * 4;
        int k = (int)(e & 2047);
        size_t qh = e >> 11;
        int q = (int)(qh & 2047);
        int h = (int)(qh >> 11);
        const float* t = &g_tab[h * 4096 + (k - q) + 2047];
        *(float4*)&out[e] = make_float4(t[0], t[1], t[2], t[3]);
    }
}

// ---------------- fp32 -> bf16 hi/lo split ----------------
__global__ void split_kernel(const float* __restrict__ src,
                             __nv_bfloat16* __restrict__ hi,
                             __nv_bfloat16* __restrict__ lo, int n4)
{
    int i = blockIdx.x * blockDim.x + threadIdx.x;
    if (i >= n4) return;
    float4 v = ((const float4*)src)[i];
    __nv_bfloat16 h0 = __float2bfloat16(v.x), h1 = __float2bfloat16(v.y);
    __nv_bfloat16 h2 = __float2bfloat16(v.z), h3 = __float2bfloat16(v.w);
    __nv_bfloat16 l0 = __float2bfloat16(v.x - __bfloat162float(h0));
    __nv_bfloat16 l1 = __float2bfloat16(v.y - __bfloat162float(h1));
    __nv_bfloat16 l2 = __float2bfloat16(v.z - __bfloat162float(h2));
    __nv_bfloat16 l3 = __float2bfloat16(v.w - __bfloat162float(h3));
    __nv_bfloat162 ph0; ph0.x = h0; ph0.y = h1;
    __nv_bfloat162 ph1; ph1.x = h2; ph1.y = h3;
    __nv_bfloat162 pl0; pl0.x = l0; pl0.y = l1;
    __nv_bfloat162 pl1; pl1.x = l2; pl1.y = l3;
    ((__nv_bfloat162*)hi)[2 * i]     = ph0;
    ((__nv_bfloat162*)hi)[2 * i + 1] = ph1;
    ((__nv_bfloat162*)lo)[2 * i]     = pl0;
    ((__nv_bfloat162*)lo)[2 * i + 1] = pl1;
}

// ---------------- mma.sync bf16 split GEMM: Y = X @ W^T ----------------
// TN gemm: A [M,K] row-major, B [N,K] row-major (both k-contiguous).
// CTA = 128x128, 512 threads (16 warps, 4x4; warp = 32x32).
// K-chunk 32, double-buffered smem, rows padded to 80B (conflict-free ldmatrix).
#define ROWB 80                       // bytes per smem row (32 bf16 + 8 pad)
#define TILEB (128 * ROWB)            // 10240 per tile
#define STAGEB (4 * TILEB)            // Ah, Al, Bh, Bl
#define GEMM_SMEM (2 * STAGEB)        // 81920

__global__ __launch_bounds__(512, 1) void gemm_mma(
    const __nv_bfloat16* __restrict__ Ah, const __nv_bfloat16* __restrict__ Al,
    const __nv_bfloat16* __restrict__ Bh, const __nv_bfloat16* __restrict__ Bl,
    float* __restrict__ Y, int permute)
{
    extern __shared__ char smem[];
    const uint32_t sb = smem_u32(smem);
    const int tid  = threadIdx.x;
    const int lane = tid & 31;
    const int wid  = tid >> 5;
    const int wm   = wid >> 2;        // 0..3  (m offset = wm*32)
    const int wn   = wid & 3;         // 0..3  (n offset = wn*32)
    const int bm = blockIdx.y * 128, bn = blockIdx.x * 128;

    // ---- load mapping: each thread owns one 16B chunk per tile ----
    const int lrow = tid >> 2;        // 0..127
    const int lch  = tid & 3;         // 0..3
    const __nv_bfloat16* gAh = Ah + (size_t)(bm + lrow) * 1024 + lch * 8;
    const __nv_bfloat16* gAl = Al + (size_t)(bm + lrow) * 1024 + lch * 8;
    const __nv_bfloat16* gBh = Bh + (size_t)(bn + lrow) * 1024 + lch * 8;
    const __nv_bfloat16* gBl = Bl + (size_t)(bn + lrow) * 1024 + lch * 8;
    const uint32_t soff = lrow * ROWB + lch * 16;

    // ---- ldmatrix lane addressing ----
    const int j = lane >> 3, r = lane & 7;
    // A: matrices (rows0-7,k0) (rows8-15,k0) (rows0-7,k8) (rows8-15,k8)
    const uint32_t a_row = wm * 32 + r + (j & 1) * 8;
    const uint32_t a_col = (j >> 1) * 8;
    // B: matrices (n0-7,k0) (n0-7,k8) (n8-15,k0) (n8-15,k8) -> frags 2f, 2f+1
    const uint32_t b_row = wn * 32 + r + (j >> 1) * 8;
    const uint32_t b_col = (j & 1) * 8;

    float acc[2][4][4];
#pragma unroll
    for (int mt = 0; mt < 2; mt++)
#pragma unroll
        for (int nf = 0; nf < 4; nf++)
#pragma unroll
            for (int e = 0; e < 4; e++) acc[mt][nf][e] = 0.f;

#define LOAD_STAGE(BUF, K0)                                                \
    {                                                                      \
        uint32_t d = sb + (BUF) * STAGEB + soff;                           \
        cp16(d,             gAh + (K0));                                   \
        cp16(d + TILEB,     gAl + (K0));                                   \
        cp16(d + 2 * TILEB, gBh + (K0));                                   \
        cp16(d + 3 * TILEB, gBl + (K0));                                   \
        CP_COMMIT();                                                       \
    }

    LOAD_STAGE(0, 0)
    CP_WAIT0();
    __syncthreads();

    for (int it = 0; it < 32; it++) {
        const int cur = it & 1;
        if (it + 1 < 32) LOAD_STAGE((it + 1) & 1, (it + 1) * 32)

        const uint32_t base = sb + cur * STAGEB;
        const uint32_t aAh = base + a_row * ROWB + a_col * 2;
        const uint32_t aAl = aAh + TILEB;
        const uint32_t aBh = base + 2 * TILEB + b_row * ROWB + b_col * 2;
        const uint32_t aBl = aBh + TILEB;

#pragma unroll
        for (int kc = 0; kc < 2; kc++) {
            const uint32_t ko = kc * 32;   // 16 bf16 = 32 bytes
            uint32_t ah[2][4], al[2][4], bh[4][2], bl[4][2];
#pragma unroll
            for (int mt = 0; mt < 2; mt++) {
                ldsm4(ah[mt], aAh + mt * (16 * ROWB) + ko);
                ldsm4(al[mt], aAl + mt * (16 * ROWB) + ko);
            }
#pragma unroll
            for (int f = 0; f < 2; f++) {
                uint32_t t[4];
                ldsm4(t, aBh + f * (16 * ROWB) + ko);
                bh[2 * f][0] = t[0]; bh[2 * f][1] = t[1];
                bh[2 * f + 1][0] = t[2]; bh[2 * f + 1][1] = t[3];
                ldsm4(t, aBl + f * (16 * ROWB) + ko);
                bl[2 * f][0] = t[0]; bl[2 * f][1] = t[1];
                bl[2 * f + 1][0] = t[2]; bl[2 * f + 1][1] = t[3];
            }
#pragma unroll
            for (int mt = 0; mt < 2; mt++)
#pragma unroll
                for (int nf = 0; nf < 4; nf++) {
                    mma16816(acc[mt][nf], ah[mt], bh[nf]);
                    mma16816(acc[mt][nf], al[mt], bh[nf]);
                    mma16816(acc[mt][nf], ah[mt], bl[nf]);
                }
        }
        if (it + 1 < 32) CP_WAIT0();
        __syncthreads();
    }
#undef LOAD_STAGE

    // ---- epilogue: write fp32 ----
#pragma unroll
    for (int mt = 0; mt < 2; mt++) {
#pragma unroll
        for (int nf = 0; nf < 4; nf++) {
            int row0 = bm + wm * 32 + mt * 16 + (lane >> 2);
            int col  = bn + wn * 32 + nf * 8 + (lane & 3) * 2;
            float2 v0 = make_float2(acc[mt][nf][0], acc[mt][nf][1]);
            float2 v1 = make_float2(acc[mt][nf][2], acc[mt][nf][3]);
            if (!permute) {
                *(float2*)&Y[(size_t)row0 * 1024 + col] = v0;
                *(float2*)&Y[(size_t)(row0 + 8) * 1024 + col] = v1;
            } else {
                int h = col >> 6, d = col & 63;
                int b0 = row0 >> 11, t0 = row0 & 2047;
                int r1 = row0 + 8;
                int b1 = r1 >> 11, t1 = r1 & 2047;
                *(float2*)&Y[(((size_t)(b0 * 16 + h) * 2048 + t0) << 6) + d] = v0;
                *(float2*)&Y[(((size_t)(b1 * 16 + h) * 2048 + t1) << 6) + d] = v1;
            }
        }
    }
}

// ---------------- flash attention (fp32, unchanged) ----------------
#define QT 128
#define KT 64
#define QS_STRIDE 132
#define KS_STRIDE 68
#define SM_QS 0
#define SM_KS (64 * QS_STRIDE)
#define SM_VS (SM_KS + 64 * KS_STRIDE)
#define SM_PS (SM_VS + 64 * 64)
#define SM_BS (SM_PS + 128 * 64)
#define SM_FLOATS (SM_BS + 256)

__global__ __launch_bounds__(256, 2) void attn_kernel()
{
    extern __shared__ float smf[];
    float* Qs = smf + SM_QS;
    float* Ks = smf + SM_KS;
    float* Vs = smf + SM_VS;
    float* Ps = smf + SM_PS;
    float* bs = smf + SM_BS;

    const int tid = threadIdx.x;
    const int bh  = blockIdx.y;
    const int h   = bh & 15;
    const int q0  = blockIdx.x * QT;
    const float* qb = g_q + (size_t)bh * T_LEN * 64;
    const float* kb = g_k + (size_t)bh * T_LEN * 64;
    const float* vb = g_v + (size_t)bh * T_LEN * 64;

#pragma unroll
    for (int i = 0; i < 8; i++) {
        int f = tid + i * 256;
        int r = f >> 4;
        int d4 = (f & 15) << 2;
        float4 v = *(const float4*)&qb[(size_t)(q0 + r) * 64 + d4];
        Qs[(d4 + 0) * QS_STRIDE + r] = v.x;
        Qs[(d4 + 1) * QS_STRIDE + r] = v.y;
        Qs[(d4 + 2) * QS_STRIDE + r] = v.z;
        Qs[(d4 + 3) * QS_STRIDE + r] = v.w;
    }

    const int tx = tid & 15, ty = tid >> 4;
    const int row0 = ty * 8, col0 = tx * 4;

    float m[8], l[8], o[8][4];
#pragma unroll
    for (int i = 0; i < 8; i++) {
        m[i] = -1e30f; l[i] = 0.f;
#pragma unroll
        for (int j = 0; j < 4; j++) o[i][j] = 0.f;
    }

    for (int kt = 0; kt < T_LEN; kt += KT) {
        __syncthreads();
#pragma unroll
        for (int i = 0; i < 4; i++) {
            int f = tid + i * 256;
            int c = f >> 4;
            int d4 = (f & 15) << 2;
            float4 v = *(const float4*)&kb[(size_t)(kt + c) * 64 + d4];
            Ks[(d4 + 0) * KS_STRIDE + c] = v.x;
            Ks[(d4 + 1) * KS_STRIDE + c] = v.y;
            Ks[(d4 + 2) * KS_STRIDE + c] = v.z;
            Ks[(d4 + 3) * KS_STRIDE + c] = v.w;
        }
#pragma unroll
        for (int i = 0; i < 4; i++) {
            int f = tid + i * 256;
            *(float4*)&Vs[f * 4] = *(const float4*)&vb[(size_t)kt * 64 + f * 4];
        }
        if (tid < 192) bs[tid] = g_tab[h * 4096 + (kt - q0) + tid + 1920];
        __syncthreads();

        float s[8][4];
#pragma unroll
        for (int i = 0; i < 8; i++)
#pragma unroll
            for (int j = 0; j < 4; j++) s[i][j] = 0.f;

#pragma unroll 8
        for (int d = 0; d < 64; d++) {
            float4 qa = *(const float4*)&Qs[d * QS_STRIDE + row0];
            float4 qc = *(const float4*)&Qs[d * QS_STRIDE + row0 + 4];
            float4 kv = *(const float4*)&Ks[d * KS_STRIDE + col0];
            float qv[8] = {qa.x, qa.y, qa.z, qa.w, qc.x, qc.y, qc.z, qc.w};
            float kk4[4] = {kv.x, kv.y, kv.z, kv.w};
#pragma unroll
            for (int i = 0; i < 8; i++)
#pragma unroll
                for (int j = 0; j < 4; j++)
                    s[i][j] = fmaf(qv[i], kk4[j], s[i][j]);
        }

#pragma unroll
        for (int i = 0; i < 8; i++) {
            int base = col0 - (row0 + i) + 127;
#pragma unroll
            for (int j = 0; j < 4; j++)
                s[i][j] = fmaf(s[i][j], 0.125f, bs[base + j]);
            float mt = fmaxf(fmaxf(s[i][0], s[i][1]), fmaxf(s[i][2], s[i][3]));
#pragma unroll
            for (int off = 1; off < 16; off <<= 1)
                mt = fmaxf(mt, __shfl_xor_sync(0xffffffffu, mt, off, 16));
            float mn = fmaxf(m[i], mt);
            float corr = expf(m[i] - mn);
            float sum = 0.f;
#pragma unroll
            for (int j = 0; j < 4; j++) {
                float p = expf(s[i][j] - mn);
                s[i][j] = p;
                sum += p;
            }
#pragma unroll
            for (int off = 1; off < 16; off <<= 1)
                sum += __shfl_xor_sync(0xffffffffu, sum, off, 16);
            l[i] = l[i] * corr + sum;
            m[i] = mn;
#pragma unroll
            for (int j = 0; j < 4; j++) o[i][j] *= corr;
            *(float4*)&Ps[(row0 + i) * 64 + col0] =
                make_float4(s[i][0], s[i][1], s[i][2], s[i][3]);
        }
        __syncthreads();

#pragma unroll 4
        for (int c = 0; c < 64; c++) {
            float4 vv = *(const float4*)&Vs[c * 64 + col0];
#pragma unroll
            for (int i = 0; i < 8; i++) {
                float p = Ps[(row0 + i) * 64 + c];
                o[i][0] = fmaf(p, vv.x, o[i][0]);
                o[i][1] = fmaf(p, vv.y, o[i][1]);
                o[i][2] = fmaf(p, vv.z, o[i][2]);
                o[i][3] = fmaf(p, vv.w, o[i][3]);
            }
        }
    }

    const int b = bh >> 4;
#pragma unroll
    for (int i = 0; i < 8; i++) {
        float inv = 1.f / l[i];
        *(float4*)&g_ao[(size_t)(b * T_LEN + q0 + row0 + i) * 1024 + h * 64 + col0] =
            make_float4(o[i][0] * inv, o[i][1] * inv, o[i][2] * inv, o[i][3] * inv);
    }
}

// ---------------- launch ----------------
extern "C" void kernel_launch(void* const* d_in, const int* in_sizes, int n_in,
                              void* d_out, int out_size)
{
    const float* query = (const float*)d_in[0];
    const float* key_  = (const float*)d_in[1];
    const float* value = (const float*)d_in[2];
    const float* Wq  = (const float*)d_in[3];
    const float* Wk  = (const float*)d_in[4];
    const float* Wv  = (const float*)d_in[5];
    const float* Wo  = (const float*)d_in[6];
    const float* rel = (const float*)d_in[7];
    float* out = (float*)d_out;

    float *gq, *gk, *gv, *gao;
    __nv_bfloat16 *ah, *al, *wh, *wl;
    cudaGetSymbolAddress((void**)&gq,  g_q);
    cudaGetSymbolAddress((void**)&gk,  g_k);
    cudaGetSymbolAddress((void**)&gv,  g_v);
    cudaGetSymbolAddress((void**)&gao, g_ao);
    cudaGetSymbolAddress((void**)&ah,  g_ah);
    cudaGetSymbolAddress((void**)&al,  g_al);
    cudaGetSymbolAddress((void**)&wh,  g_wh);
    cudaGetSymbolAddress((void**)&wl,  g_wl);

    cudaFuncSetAttribute(attn_kernel, cudaFuncAttributeMaxDynamicSharedMemorySize,
                         SM_FLOATS * 4);
    cudaFuncSetAttribute(gemm_mma, cudaFuncAttributeMaxDynamicSharedMemorySize,
                         GEMM_SMEM);

    bias_tab_kernel<<<256, 256>>>(rel);

    const int NX4 = M_ROWS * D_MODEL / 4;       // 2M
    const int NW4 = D_MODEL * D_MODEL / 4;      // 256K
    dim3 gg(8, 64);

    split_kernel<<<NX4 / 256, 256>>>(query, ah, al, NX4);
    split_kernel<<<NW4 / 256, 256>>>(Wq, wh, wl, NW4);
    gemm_mma<<<gg, 512, GEMM_SMEM>>>(ah, al, wh, wl, gq, 1);

    split_kernel<<<NX4 / 256, 256>>>(key_, ah, al, NX4);
    split_kernel<<<NW4 / 256, 256>>>(Wk, wh, wl, NW4);
    gemm_mma<<<gg, 512, GEMM_SMEM>>>(ah, al, wh, wl, gk, 1);

    split_kernel<<<NX4 / 256, 256>>>(value, ah, al, NX4);
    split_kernel<<<NW4 / 256, 256>>>(Wv, wh, wl, NW4);
    gemm_mma<<<gg, 512, GEMM_SMEM>>>(ah, al, wh, wl, gv, 1);

    attn_kernel<<<dim3(16, 64), 256, SM_FLOATS * 4>>>();

    split_kernel<<<NX4 / 256, 256>>>(gao, ah, al, NX4);
    split_kernel<<<NW4 / 256, 256>>>(Wo, wh, wl, NW4);
    gemm_mma<<<gg, 512, GEMM_SMEM>>>(ah, al, wh, wl, out, 0);

    // second tuple element: position_bias [1,16,2048,2048]
    if ((long long)out_size >= 8388608LL + 67108864LL)
        bias_out_kernel<<<2048, 256>>>(out + 8388608);
}

// round 5
// speedup vs baseline: 2.3225x; 1.7151x over previous
#include <cuda_runtime.h>
#include <cuda_bf16.h>
#include <math.h>
#include <stdint.h>

#define D_MODEL 1024
#define N_HEADS 16
#define D_HEAD  64
#define B_SZ    4
#define T_LEN   2048
#define M_ROWS  (B_SZ * T_LEN)   // 8192

// ---------------- scratch (static device globals; no allocs) ----------------
__device__ float g_tab[N_HEADS * 4096];
__device__ __nv_bfloat16 g_ah[(size_t)M_ROWS * D_MODEL];  // activation hi
__device__ __nv_bfloat16 g_al[(size_t)M_ROWS * D_MODEL];  // activation lo
__device__ __nv_bfloat16 g_wh[(size_t)D_MODEL * D_MODEL]; // weight hi
__device__ __nv_bfloat16 g_wl[(size_t)D_MODEL * D_MODEL]; // weight lo
__device__ __nv_bfloat16 g_qh[(size_t)M_ROWS * D_MODEL];  // [B,H,T,Dh] hi
__device__ __nv_bfloat16 g_ql[(size_t)M_ROWS * D_MODEL];
__device__ __nv_bfloat16 g_kh[(size_t)M_ROWS * D_MODEL];
__device__ __nv_bfloat16 g_kl[(size_t)M_ROWS * D_MODEL];
__device__ __nv_bfloat16 g_vh[(size_t)M_ROWS * D_MODEL];
__device__ __nv_bfloat16 g_vl[(size_t)M_ROWS * D_MODEL];

// ---------------- PTX helpers (baseline sm_103) ----------------
__device__ __forceinline__ uint32_t smem_u32(const void* p) {
    uint32_t a;
    asm("{ .reg .u64 t; cvta.to.shared.u64 t, %1; cvt.u32.u64 %0, t; }" : "=r"(a) : "l"(p));
    return a;
}
__device__ __forceinline__ void cp16(uint32_t dst, const void* src) {
    asm volatile("cp.async.cg.shared.global [%0], [%1], 16;" :: "r"(dst), "l"(src));
}
#define CP_COMMIT() asm volatile("cp.async.commit_group;" ::: "memory")
#define CP_WAIT0()  asm volatile("cp.async.wait_group 0;" ::: "memory")
#define CP_WAIT1()  asm volatile("cp.async.wait_group 1;" ::: "memory")

__device__ __forceinline__ void ldsm4(uint32_t* r, uint32_t addr) {
    asm volatile("ldmatrix.sync.aligned.m8n8.x4.shared.b16 {%0,%1,%2,%3}, [%4];"
                 : "=r"(r[0]), "=r"(r[1]), "=r"(r[2]), "=r"(r[3]) : "r"(addr));
}
__device__ __forceinline__ void ldsm4t(uint32_t* r, uint32_t addr) {
    asm volatile("ldmatrix.sync.aligned.m8n8.x4.trans.shared.b16 {%0,%1,%2,%3}, [%4];"
                 : "=r"(r[0]), "=r"(r[1]), "=r"(r[2]), "=r"(r[3]) : "r"(addr));
}
__device__ __forceinline__ void mma16816(float* c, const uint32_t* a, const uint32_t* b) {
    asm volatile(
        "mma.sync.aligned.m16n8k16.row.col.f32.bf16.bf16.f32 "
        "{%0,%1,%2,%3}, {%4,%5,%6,%7}, {%8,%9}, {%0,%1,%2,%3};"
        : "+f"(c[0]), "+f"(c[1]), "+f"(c[2]), "+f"(c[3])
        : "r"(a[0]), "r"(a[1]), "r"(a[2]), "r"(a[3]), "r"(b[0]), "r"(b[1]));
}
// pack two f32 -> bf16x2 (f0 in low half, f1 in high half)
__device__ __forceinline__ uint32_t pack_bf2(float f0, float f1) {
    uint32_t r;
    asm("cvt.rn.bf16x2.f32 %0, %1, %2;" : "=r"(r) : "f"(f1), "f"(f0));
    return r;
}
__device__ __forceinline__ float bf2_lo(uint32_t p) { return __uint_as_float(p << 16); }
__device__ __forceinline__ float bf2_hi(uint32_t p) { return __uint_as_float(p & 0xffff0000u); }

// ---------------- bias bucket table ----------------
__global__ void bias_tab_kernel(const float* __restrict__ rel_emb)
{
    int idx = blockIdx.x * blockDim.x + threadIdx.x;
    if (idx >= N_HEADS * 4095) return;
    int h  = idx / 4095;
    int dp = idx % 4095;
    int r  = dp - 2047;
    int bucket = (r > 0) ? 16 : 0;
    int rp = (r < 0) ? -r : r;
    int rel;
    if (rp < 8) {
        rel = rp;
    } else {
        float v = (logf((float)rp * 0.125f) / 2.772588722239781f) * 8.0f;
        rel = 8 + (int)v;
        if (rel > 15) rel = 15;
    }
    bucket += rel;
    g_tab[h * 4096 + dp] = rel_emb[bucket * N_HEADS + h];
}

// ---------------- position_bias tensor writer ----------------
__global__ void bias_out_kernel(float* __restrict__ out)
{
    const size_t n4 = (size_t)N_HEADS * T_LEN * T_LEN / 4;
    for (size_t i = (size_t)blockIdx.x * blockDim.x + threadIdx.x; i < n4;
         i += (size_t)gridDim.x * blockDim.x) {
        size_t e = i * 4;
        int k = (int)(e & 2047);
        size_t qh = e >> 11;
        int q = (int)(qh & 2047);
        int h = (int)(qh >> 11);
        const float* t = &g_tab[h * 4096 + (k - q) + 2047];
        *(float4*)&out[e] = make_float4(t[0], t[1], t[2], t[3]);
    }
}

// ---------------- fp32 -> bf16 hi/lo split ----------------
__global__ void split_kernel(const float* __restrict__ src,
                             __nv_bfloat16* __restrict__ hi,
                             __nv_bfloat16* __restrict__ lo, int n4)
{
    int i = blockIdx.x * blockDim.x + threadIdx.x;
    if (i >= n4) return;
    float4 v = ((const float4*)src)[i];
    uint32_t h0 = pack_bf2(v.x, v.y);
    uint32_t h1 = pack_bf2(v.z, v.w);
    uint32_t l0 = pack_bf2(v.x - bf2_lo(h0), v.y - bf2_hi(h0));
    uint32_t l1 = pack_bf2(v.z - bf2_lo(h1), v.w - bf2_hi(h1));
    ((uint32_t*)hi)[2 * i]     = h0;
    ((uint32_t*)hi)[2 * i + 1] = h1;
    ((uint32_t*)lo)[2 * i]     = l0;
    ((uint32_t*)lo)[2 * i + 1] = l1;
}

// ---------------- mma.sync bf16 split GEMM: Y = X @ W^T ----------------
// mode 0: fp32 plain [M,1024] to Y.
// mode 2: bf16 hi/lo split, permuted to [B,H,T,Dh], to Yh/Yl.
#define ROWB 80
#define TILEB (128 * ROWB)
#define STAGEB (4 * TILEB)
#define GEMM_SMEM (2 * STAGEB)

__global__ __launch_bounds__(512, 1) void gemm_mma(
    const __nv_bfloat16* __restrict__ Ah, const __nv_bfloat16* __restrict__ Al,
    const __nv_bfloat16* __restrict__ Bh, const __nv_bfloat16* __restrict__ Bl,
    float* __restrict__ Y, __nv_bfloat16* __restrict__ Yh,
    __nv_bfloat16* __restrict__ Yl, int mode)
{
    extern __shared__ char smem[];
    const uint32_t sb = smem_u32(smem);
    const int tid  = threadIdx.x;
    const int lane = tid & 31;
    const int wid  = tid >> 5;
    const int wm   = wid >> 2;
    const int wn   = wid & 3;
    const int bm = blockIdx.y * 128, bn = blockIdx.x * 128;

    const int lrow = tid >> 2;
    const int lch  = tid & 3;
    const __nv_bfloat16* gAh = Ah + (size_t)(bm + lrow) * 1024 + lch * 8;
    const __nv_bfloat16* gAl = Al + (size_t)(bm + lrow) * 1024 + lch * 8;
    const __nv_bfloat16* gBh = Bh + (size_t)(bn + lrow) * 1024 + lch * 8;
    const __nv_bfloat16* gBl = Bl + (size_t)(bn + lrow) * 1024 + lch * 8;
    const uint32_t soff = lrow * ROWB + lch * 16;

    const int j = lane >> 3, r = lane & 7;
    const uint32_t a_row = wm * 32 + r + (j & 1) * 8;
    const uint32_t a_col = (j >> 1) * 8;
    const uint32_t b_row = wn * 32 + r + (j >> 1) * 8;
    const uint32_t b_col = (j & 1) * 8;

    float acc[2][4][4];
#pragma unroll
    for (int mt = 0; mt < 2; mt++)
#pragma unroll
        for (int nf = 0; nf < 4; nf++)
#pragma unroll
            for (int e = 0; e < 4; e++) acc[mt][nf][e] = 0.f;

#define LOAD_STAGE(BUF, K0)                                                \
    {                                                                      \
        uint32_t d = sb + (BUF) * STAGEB + soff;                           \
        cp16(d,             gAh + (K0));                                   \
        cp16(d + TILEB,     gAl + (K0));                                   \
        cp16(d + 2 * TILEB, gBh + (K0));                                   \
        cp16(d + 3 * TILEB, gBl + (K0));                                   \
        CP_COMMIT();                                                       \
    }

    LOAD_STAGE(0, 0)
    CP_WAIT0();
    __syncthreads();

    for (int it = 0; it < 32; it++) {
        const int cur = it & 1;
        if (it + 1 < 32) LOAD_STAGE((it + 1) & 1, (it + 1) * 32)

        const uint32_t base = sb + cur * STAGEB;
        const uint32_t aAh = base + a_row * ROWB + a_col * 2;
        const uint32_t aAl = aAh + TILEB;
        const uint32_t aBh = base + 2 * TILEB + b_row * ROWB + b_col * 2;
        const uint32_t aBl = aBh + TILEB;

#pragma unroll
        for (int kc = 0; kc < 2; kc++) {
            const uint32_t ko = kc * 32;
            uint32_t ah[2][4], al[2][4], bh[4][2], bl[4][2];
#pragma unroll
            for (int mt = 0; mt < 2; mt++) {
                ldsm4(ah[mt], aAh + mt * (16 * ROWB) + ko);
                ldsm4(al[mt], aAl + mt * (16 * ROWB) + ko);
            }
#pragma unroll
            for (int f = 0; f < 2; f++) {
                uint32_t t[4];
                ldsm4(t, aBh + f * (16 * ROWB) + ko);
                bh[2 * f][0] = t[0]; bh[2 * f][1] = t[1];
                bh[2 * f + 1][0] = t[2]; bh[2 * f + 1][1] = t[3];
                ldsm4(t, aBl + f * (16 * ROWB) + ko);
                bl[2 * f][0] = t[0]; bl[2 * f][1] = t[1];
                bl[2 * f + 1][0] = t[2]; bl[2 * f + 1][1] = t[3];
            }
#pragma unroll
            for (int mt = 0; mt < 2; mt++)
#pragma unroll
                for (int nf = 0; nf < 4; nf++) {
                    mma16816(acc[mt][nf], ah[mt], bh[nf]);
                    mma16816(acc[mt][nf], al[mt], bh[nf]);
                    mma16816(acc[mt][nf], ah[mt], bl[nf]);
                }
        }
        if (it + 1 < 32) CP_WAIT0();
        __syncthreads();
    }
#undef LOAD_STAGE

#pragma unroll
    for (int mt = 0; mt < 2; mt++) {
#pragma unroll
        for (int nf = 0; nf < 4; nf++) {
            int row0 = bm + wm * 32 + mt * 16 + (lane >> 2);
            int col  = bn + wn * 32 + nf * 8 + (lane & 3) * 2;
            if (mode == 0) {
                *(float2*)&Y[(size_t)row0 * 1024 + col] =
                    make_float2(acc[mt][nf][0], acc[mt][nf][1]);
                *(float2*)&Y[(size_t)(row0 + 8) * 1024 + col] =
                    make_float2(acc[mt][nf][2], acc[mt][nf][3]);
            } else {
                int h = col >> 6, d = col & 63;
#pragma unroll
                for (int rr2 = 0; rr2 < 2; rr2++) {
                    int row = row0 + rr2 * 8;
                    int b = row >> 11, t = row & 2047;
                    float f0 = acc[mt][nf][2 * rr2], f1 = acc[mt][nf][2 * rr2 + 1];
                    uint32_t hp = pack_bf2(f0, f1);
                    uint32_t lp = pack_bf2(f0 - bf2_lo(hp), f1 - bf2_hi(hp));
                    size_t idx = (((size_t)(b * 16 + h) * 2048 + t) << 6) + d;
                    *(uint32_t*)&Yh[idx] = hp;
                    *(uint32_t*)&Yl[idx] = lp;
                }
            }
        }
    }
}

// ---------------- mma.sync flash attention (bf16 split) ----------------
// grid (16 q-tiles, 64 bh), 256 threads = 8 warps, warp = 16 q-rows x 64 cols.
// KT = 64 keys/iter, double-buffered K/V hi/lo via cp.async.
#define AROWB 144                         // 64 bf16 + 16B pad
#define KVTILE (64 * AROWB)               // 9216
#define KVBUF  (4 * KVTILE)               // Kh,Kl,Vh,Vl = 36864
#define ATT_SMEM (2 * KVBUF + 768)        // + bias window (192 f32)

__global__ __launch_bounds__(256, 1) void attn_mma()
{
    extern __shared__ char smem[];
    const uint32_t sb = smem_u32(smem);
    float* bsf = (float*)(smem + 2 * KVBUF);
    const int tid = threadIdx.x, lane = tid & 31, wid = tid >> 5;
    const int bh = blockIdx.y, h = bh & 15;
    const int q0 = blockIdx.x * 128;
    const size_t base = (size_t)bh * T_LEN * 64;
    const __nv_bfloat16* qhp = g_qh + base + (size_t)q0 * 64;
    const __nv_bfloat16* qlp = g_ql + base + (size_t)q0 * 64;
    const __nv_bfloat16* khp = g_kh + base;
    const __nv_bfloat16* klp = g_kl + base;
    const __nv_bfloat16* vhp = g_vh + base;
    const __nv_bfloat16* vlp = g_vl + base;

    // ---- stage Q (hi at buf0, lo at buf0+18432), load A-frags, then free buf0
#pragma unroll
    for (int i = 0; i < 4; i++) {
        int idx = i * 256 + tid;
        int row = idx >> 3, ch = idx & 7;
        cp16(sb + row * AROWB + ch * 16, qhp + (size_t)row * 64 + ch * 8);
        cp16(sb + 2 * KVTILE + row * AROWB + ch * 16, qlp + (size_t)row * 64 + ch * 8);
    }
    CP_COMMIT();
    CP_WAIT0();
    __syncthreads();

    const int j = lane >> 3, rr = lane & 7;
    uint32_t qfh[4][4], qfl[4][4];
    {
        uint32_t qa = sb + (uint32_t)(wid * 16 + rr + (j & 1) * 8) * AROWB + (j >> 1) * 16;
#pragma unroll
        for (int kc = 0; kc < 4; kc++) {
            ldsm4(qfh[kc], qa + kc * 32);
            ldsm4(qfl[kc], qa + 2 * KVTILE + kc * 32);
        }
    }
    __syncthreads();

#define LOADKV(BUF, KT0)                                                     \
    {                                                                        \
        uint32_t d = sb + (BUF) * KVBUF;                                     \
        _Pragma("unroll")                                                    \
        for (int i = 0; i < 2; i++) {                                        \
            int idx = i * 256 + tid;                                         \
            int row = idx >> 3, ch = idx & 7;                                \
            uint32_t o = row * AROWB + ch * 16;                              \
            size_t g = (size_t)((KT0) + row) * 64 + ch * 8;                  \
            cp16(d + o,              khp + g);                               \
            cp16(d + KVTILE + o,     klp + g);                               \
            cp16(d + 2 * KVTILE + o, vhp + g);                               \
            cp16(d + 3 * KVTILE + o, vlp + g);                               \
        }                                                                    \
        CP_COMMIT();                                                         \
    }

    float s[8][4], o[8][4], mv[2], lv[2];
#pragma unroll
    for (int nf = 0; nf < 8; nf++)
#pragma unroll
        for (int e = 0; e < 4; e++) o[nf][e] = 0.f;
    mv[0] = mv[1] = -1e30f;
    lv[0] = lv[1] = 0.f;

    const int cbase = (lane & 3) * 2;
    const int rbase = wid * 16 + (lane >> 2);

    LOADKV(0, 0)

    for (int it = 0; it < 32; it++) {
        const int kt = it * 64;
        if (it + 1 < 32) {
            LOADKV((it + 1) & 1, kt + 64)
            CP_WAIT1();
        } else {
            CP_WAIT0();
        }
        if (tid < 192) bsf[tid] = g_tab[h * 4096 + (kt - q0) + tid + 1920];
        __syncthreads();

        const uint32_t kbase = sb + (it & 1) * KVBUF;
        const uint32_t vbase = kbase + 2 * KVTILE;

        // ---- S = Q K^T (3-product split) ----
#pragma unroll
        for (int nf = 0; nf < 8; nf++)
#pragma unroll
            for (int e = 0; e < 4; e++) s[nf][e] = 0.f;

#pragma unroll
        for (int kc = 0; kc < 4; kc++) {
#pragma unroll
            for (int np = 0; np < 4; np++) {
                uint32_t kf[4], kfl[4];
                uint32_t ka = kbase + (uint32_t)(np * 16 + (j >> 1) * 8 + rr) * AROWB
                              + (j & 1) * 16 + kc * 32;
                ldsm4(kf, ka);
                ldsm4(kfl, ka + KVTILE);
                mma16816(s[2 * np],     qfh[kc], kf);
                mma16816(s[2 * np],     qfl[kc], kf);
                mma16816(s[2 * np],     qfh[kc], kfl);
                mma16816(s[2 * np + 1], qfh[kc], kf + 2);
                mma16816(s[2 * np + 1], qfl[kc], kf + 2);
                mma16816(s[2 * np + 1], qfh[kc], kfl + 2);
            }
        }

        // ---- scale + bias + online softmax ----
#pragma unroll
        for (int nf = 0; nf < 8; nf++)
#pragma unroll
            for (int e = 0; e < 4; e++) {
                int ri = e >> 1, cc = e & 1;
                int bidx = nf * 8 + cbase + cc - (rbase + ri * 8) + 127;
                s[nf][e] = fmaf(s[nf][e], 0.125f, bsf[bidx]);
            }

#pragma unroll
        for (int ri = 0; ri < 2; ri++) {
            float mr = -1e30f;
#pragma unroll
            for (int nf = 0; nf < 8; nf++)
                mr = fmaxf(mr, fmaxf(s[nf][2 * ri], s[nf][2 * ri + 1]));
            mr = fmaxf(mr, __shfl_xor_sync(0xffffffffu, mr, 1));
            mr = fmaxf(mr, __shfl_xor_sync(0xffffffffu, mr, 2));
            float mn = fmaxf(mv[ri], mr);
            float corr = __expf(mv[ri] - mn);
            mv[ri] = mn;
            float sum = 0.f;
#pragma unroll
            for (int nf = 0; nf < 8; nf++) {
                float p0 = __expf(s[nf][2 * ri] - mn);
                float p1 = __expf(s[nf][2 * ri + 1] - mn);
                s[nf][2 * ri] = p0;
                s[nf][2 * ri + 1] = p1;
                sum += p0 + p1;
            }
            sum += __shfl_xor_sync(0xffffffffu, sum, 1);
            sum += __shfl_xor_sync(0xffffffffu, sum, 2);
            lv[ri] = lv[ri] * corr + sum;
#pragma unroll
            for (int nf = 0; nf < 8; nf++) {
                o[nf][2 * ri] *= corr;
                o[nf][2 * ri + 1] *= corr;
            }
        }

        // ---- O += P V (in-register P split, V via ldmatrix.trans) ----
#pragma unroll
        for (int kc = 0; kc < 4; kc++) {
            uint32_t ph[4], pl[4];
#pragma unroll
            for (int q2 = 0; q2 < 2; q2++) {
                int nf = 2 * kc + q2;
#pragma unroll
                for (int half = 0; half < 2; half++) {
                    float f0 = s[nf][2 * half], f1 = s[nf][2 * half + 1];
                    uint32_t hp = pack_bf2(f0, f1);
                    ph[2 * q2 + half] = hp;
                    pl[2 * q2 + half] = pack_bf2(f0 - bf2_lo(hp), f1 - bf2_hi(hp));
                }
            }
#pragma unroll
            for (int np = 0; np < 4; np++) {
                uint32_t vf[4], vfl[4];
                uint32_t va = vbase + (uint32_t)(kc * 16 + (j & 1) * 8 + rr) * AROWB
                              + (np * 16 + (j >> 1) * 8) * 2;
                ldsm4t(vf, va);
                ldsm4t(vfl, va + KVTILE);
                mma16816(o[2 * np],     ph, vf);
                mma16816(o[2 * np],     pl, vf);
                mma16816(o[2 * np],     ph, vfl);
                mma16816(o[2 * np + 1], ph, vf + 2);
                mma16816(o[2 * np + 1], pl, vf + 2);
                mma16816(o[2 * np + 1], ph, vfl + 2);
            }
        }
        __syncthreads();
    }
#undef LOADKV

    // ---- epilogue: O/l -> bf16 hi/lo into g_ah/g_al [B,T,D] ----
    const int b = bh >> 4;
    float inv0 = 1.f / lv[0], inv1 = 1.f / lv[1];
#pragma unroll
    for (int nf = 0; nf < 8; nf++) {
#pragma unroll
        for (int ri = 0; ri < 2; ri++) {
            float inv = ri ? inv1 : inv0;
            int t = q0 + rbase + ri * 8;
            int col = h * 64 + nf * 8 + cbase;
            float f0 = o[nf][2 * ri] * inv, f1 = o[nf][2 * ri + 1] * inv;
            uint32_t hp = pack_bf2(f0, f1);
            uint32_t lp = pack_bf2(f0 - bf2_lo(hp), f1 - bf2_hi(hp));
            size_t idx = ((size_t)(b * 2048 + t)) * 1024 + col;
            *(uint32_t*)&g_ah[idx] = hp;
            *(uint32_t*)&g_al[idx] = lp;
        }
    }
}

// ---------------- launch ----------------
extern "C" void kernel_launch(void* const* d_in, const int* in_sizes, int n_in,
                              void* d_out, int out_size)
{
    const float* query = (const float*)d_in[0];
    const float* key_  = (const float*)d_in[1];
    const float* value = (const float*)d_in[2];
    const float* Wq  = (const float*)d_in[3];
    const float* Wk  = (const float*)d_in[4];
    const float* Wv  = (const float*)d_in[5];
    const float* Wo  = (const float*)d_in[6];
    const float* rel = (const float*)d_in[7];
    float* out = (float*)d_out;

    __nv_bfloat16 *ah, *al, *wh, *wl, *qh, *ql, *kh, *kl, *vh, *vl;
    cudaGetSymbolAddress((void**)&ah, g_ah);
    cudaGetSymbolAddress((void**)&al, g_al);
    cudaGetSymbolAddress((void**)&wh, g_wh);
    cudaGetSymbolAddress((void**)&wl, g_wl);
    cudaGetSymbolAddress((void**)&qh, g_qh);
    cudaGetSymbolAddress((void**)&ql, g_ql);
    cudaGetSymbolAddress((void**)&kh, g_kh);
    cudaGetSymbolAddress((void**)&kl, g_kl);
    cudaGetSymbolAddress((void**)&vh, g_vh);
    cudaGetSymbolAddress((void**)&vl, g_vl);

    cudaFuncSetAttribute(gemm_mma, cudaFuncAttributeMaxDynamicSharedMemorySize,
                         GEMM_SMEM);
    cudaFuncSetAttribute(attn_mma, cudaFuncAttributeMaxDynamicSharedMemorySize,
                         ATT_SMEM);

    bias_tab_kernel<<<256, 256>>>(rel);

    const int NX4 = M_ROWS * D_MODEL / 4;
    const int NW4 = D_MODEL * D_MODEL / 4;
    dim3 gg(8, 64);

    split_kernel<<<NX4 / 256, 256>>>(query, ah, al, NX4);
    split_kernel<<<NW4 / 256, 256>>>(Wq, wh, wl, NW4);
    gemm_mma<<<gg, 512, GEMM_SMEM>>>(ah, al, wh, wl, nullptr, qh, ql, 2);

    split_kernel<<<NX4 / 256, 256>>>(key_, ah, al, NX4);
    split_kernel<<<NW4 / 256, 256>>>(Wk, wh, wl, NW4);
    gemm_mma<<<gg, 512, GEMM_SMEM>>>(ah, al, wh, wl, nullptr, kh, kl, 2);

    split_kernel<<<NX4 / 256, 256>>>(value, ah, al, NX4);
    split_kernel<<<NW4 / 256, 256>>>(Wv, wh, wl, NW4);
    gemm_mma<<<gg, 512, GEMM_SMEM>>>(ah, al, wh, wl, nullptr, vh, vl, 2);

    attn_mma<<<dim3(16, 64), 256, ATT_SMEM>>>();   // writes ah/al directly

    split_kernel<<<NW4 / 256, 256>>>(Wo, wh, wl, NW4);
    gemm_mma<<<gg, 512, GEMM_SMEM>>>(ah, al, wh, wl, out, nullptr, nullptr, 0);

    if ((long long)out_size >= 8388608LL + 67108864LL)
        bias_out_kernel<<<2048, 256>>>(out + 8388608);
}